// round 6
// baseline (speedup 1.0000x reference)
#include <cuda_runtime.h>
#include <cuda_bf16.h>
#include <cstdint>

#define NNODES 100000
#define RELS   8
#define HF     128
#define NNZ_   1600000
#define CAP    128
#define TILES_M ((NNODES + 127) / 128)   // 782

// ---- static device scratch ----
__device__ int   g_cnt[NNODES];
__device__ int2  g_bucket[(size_t)NNODES * CAP];                 // {src | rel<<17, bits(val)}
__device__ __nv_bfloat16 g_ah[(size_t)RELS * NNODES * HF];       // agg hi (bf16)
__device__ __nv_bfloat16 g_al[(size_t)RELS * NNODES * HF];       // agg lo (bf16 residual)
__device__ __nv_bfloat16 g_bh[RELS * HF * HF];                   // W hi
__device__ __nv_bfloat16 g_bl[RELS * HF * HF];                   // W lo

// ============================================================================
// helpers (family-portable PTX only: cp.async, ldmatrix, mma.sync)
// ============================================================================
__device__ __forceinline__ uint32_t smem_u32(const void* p) {
    uint32_t a;
    asm("{ .reg .u64 t; cvta.to.shared.u64 t, %1; cvt.u32.u64 %0, t; }" : "=r"(a) : "l"(p));
    return a;
}
__device__ __forceinline__ void cp16(uint32_t dst, const void* src) {
    asm volatile("cp.async.cg.shared.global [%0], [%1], 16;" :: "r"(dst), "l"(src) : "memory");
}
__device__ __forceinline__ void cp16z(uint32_t dst, const void* src, bool ok) {
    int n = ok ? 16 : 0;   // src-size 0 -> zero-fill
    asm volatile("cp.async.cg.shared.global [%0], [%1], 16, %2;" :: "r"(dst), "l"(src), "r"(n) : "memory");
}
#define CP_COMMIT() asm volatile("cp.async.commit_group;" ::: "memory")
#define CP_WAIT(N)  asm volatile("cp.async.wait_group %0;" :: "n"(N) : "memory")

__device__ __forceinline__ void ldm_x4(uint32_t& r0, uint32_t& r1, uint32_t& r2, uint32_t& r3, uint32_t a) {
    asm volatile("ldmatrix.sync.aligned.m8n8.x4.shared.b16 {%0,%1,%2,%3}, [%4];"
                 : "=r"(r0), "=r"(r1), "=r"(r2), "=r"(r3) : "r"(a));
}
__device__ __forceinline__ void mma16816(float* c, const uint32_t* a, const uint32_t* b) {
    asm volatile("mma.sync.aligned.m16n8k16.row.col.f32.bf16.bf16.f32 "
                 "{%0,%1,%2,%3}, {%4,%5,%6,%7}, {%8,%9}, {%0,%1,%2,%3};"
                 : "+f"(c[0]), "+f"(c[1]), "+f"(c[2]), "+f"(c[3])
                 : "r"(a[0]), "r"(a[1]), "r"(a[2]), "r"(a[3]), "r"(b[0]), "r"(b[1]));
}

// ============================================================================
// Phase 1: bucket edges by destination (indices are int32)
// ============================================================================
__global__ void build_buckets(const int* __restrict__ rows,
                              const int* __restrict__ cols,
                              const float* __restrict__ vals) {
    int e = blockIdx.x * blockDim.x + threadIdx.x;
    if (e >= NNZ_) return;
    int row = rows[e];
    int rel = row / NNODES;
    int dst = row - rel * NNODES;
    int src = cols[e];
    if ((unsigned)rel >= RELS || (unsigned)dst >= NNODES || (unsigned)src >= NNODES) return;
    int slot = atomicAdd(&g_cnt[dst], 1);
    if (slot < CAP)
        g_bucket[(size_t)dst * CAP + slot] = make_int2(src | (rel << 17), __float_as_int(vals[e]));
}

// ============================================================================
// Phase 1b: split W (fp32 -> bf16 hi/lo)
// ============================================================================
__global__ void convert_w(const float* __restrict__ W) {
    int i = blockIdx.x * blockDim.x + threadIdx.x;
    if (i >= RELS * HF * HF) return;
    float x = W[i];
    __nv_bfloat16 h = __float2bfloat16_rn(x);
    g_bh[i] = h;
    g_bl[i] = __float2bfloat16_rn(x - __bfloat162float(h));
}

// ============================================================================
// Phase 2: one warp per dst: agg[r][dst][:] = sum val * nodes[src][:]
// Unroll-by-4 software pipeline: 4 independent gathers in flight (MLP=4).
// ============================================================================
__device__ __forceinline__ void split_store(int rel, int dst, int lane, float4 a) {
    size_t base = ((size_t)rel * NNODES + dst) * HF + lane * 4;
    __nv_bfloat16 hx = __float2bfloat16_rn(a.x), hy = __float2bfloat16_rn(a.y);
    __nv_bfloat16 hz = __float2bfloat16_rn(a.z), hw = __float2bfloat16_rn(a.w);
    *(__nv_bfloat162*)(g_ah + base)     = __nv_bfloat162(hx, hy);
    *(__nv_bfloat162*)(g_ah + base + 2) = __nv_bfloat162(hz, hw);
    *(__nv_bfloat162*)(g_al + base) = __nv_bfloat162(
        __float2bfloat16_rn(a.x - __bfloat162float(hx)),
        __float2bfloat16_rn(a.y - __bfloat162float(hy)));
    *(__nv_bfloat162*)(g_al + base + 2) = __nv_bfloat162(
        __float2bfloat16_rn(a.z - __bfloat162float(hz)),
        __float2bfloat16_rn(a.w - __bfloat162float(hw)));
}

__global__ __launch_bounds__(256) void aggregate_feats(const float* __restrict__ nodes) {
    int warp = (blockIdx.x * blockDim.x + threadIdx.x) >> 5;
    int lane = threadIdx.x & 31;
    if (warp >= NNODES) return;
    int cnt = g_cnt[warp];
    if (cnt > CAP) cnt = CAP;

    float4 a0 = {0,0,0,0}, a1 = {0,0,0,0}, a2 = {0,0,0,0}, a3 = {0,0,0,0};
    float4 a4 = {0,0,0,0}, a5 = {0,0,0,0}, a6 = {0,0,0,0}, a7 = {0,0,0,0};

    const int2* bk = g_bucket + (size_t)warp * CAP;

    #define ACCSW(E, X) {                                                     \
        float v = __int_as_float((E).y);                                      \
        int rel = (E).x >> 17;                                                \
        switch (rel) {                                                        \
            case 0: a0.x+=v*(X).x; a0.y+=v*(X).y; a0.z+=v*(X).z; a0.w+=v*(X).w; break; \
            case 1: a1.x+=v*(X).x; a1.y+=v*(X).y; a1.z+=v*(X).z; a1.w+=v*(X).w; break; \
            case 2: a2.x+=v*(X).x; a2.y+=v*(X).y; a2.z+=v*(X).z; a2.w+=v*(X).w; break; \
            case 3: a3.x+=v*(X).x; a3.y+=v*(X).y; a3.z+=v*(X).z; a3.w+=v*(X).w; break; \
            case 4: a4.x+=v*(X).x; a4.y+=v*(X).y; a4.z+=v*(X).z; a4.w+=v*(X).w; break; \
            case 5: a5.x+=v*(X).x; a5.y+=v*(X).y; a5.z+=v*(X).z; a5.w+=v*(X).w; break; \
            case 6: a6.x+=v*(X).x; a6.y+=v*(X).y; a6.z+=v*(X).z; a6.w+=v*(X).w; break; \
            case 7: a7.x+=v*(X).x; a7.y+=v*(X).y; a7.z+=v*(X).z; a7.w+=v*(X).w; break; \
        }                                                                     \
    }

    int s = 0;
    for (; s + 4 <= cnt; s += 4) {
        int2 e0 = bk[s], e1 = bk[s+1], e2 = bk[s+2], e3 = bk[s+3];
        float4 x0 = *(const float4*)(nodes + (size_t)(e0.x & 0x1FFFF) * HF + lane * 4);
        float4 x1 = *(const float4*)(nodes + (size_t)(e1.x & 0x1FFFF) * HF + lane * 4);
        float4 x2 = *(const float4*)(nodes + (size_t)(e2.x & 0x1FFFF) * HF + lane * 4);
        float4 x3 = *(const float4*)(nodes + (size_t)(e3.x & 0x1FFFF) * HF + lane * 4);
        ACCSW(e0, x0); ACCSW(e1, x1); ACCSW(e2, x2); ACCSW(e3, x3);
    }
    for (; s < cnt; s++) {
        int2 e = bk[s];
        float4 x = *(const float4*)(nodes + (size_t)(e.x & 0x1FFFF) * HF + lane * 4);
        ACCSW(e, x);
    }
    #undef ACCSW

    split_store(0, warp, lane, a0); split_store(1, warp, lane, a1);
    split_store(2, warp, lane, a2); split_store(3, warp, lane, a3);
    split_store(4, warp, lane, a4); split_store(5, warp, lane, a5);
    split_store(6, warp, lane, a6); split_store(7, warp, lane, a7);
}

// ============================================================================
// Phase 3: out = relu( agg_flat[100k,1024] @ Wcat[128,1024]^T )
// mma.sync m16n8k16 bf16 3-pass split. Block 128x128, 8 warps 4x2.
// A double-buffered (2 stages), B single-buffered -> 110.6KB smem,
// __launch_bounds__(256,2) -> 2 CTAs/SM for latency hiding.
// ============================================================================
#define PITCH   72                        // bf16 per smem row (64 + 8 pad)
#define AT_SZ   (128 * PITCH * 2)         // 18432 B per 128x64 tile
#define SM_A(st, h)  ((uint32_t)((st) * 2 * AT_SZ + (h) * AT_SZ))
#define SM_B(h)      ((uint32_t)(4 * AT_SZ + (h) * AT_SZ))
#define SM_TOTAL     (6 * AT_SZ)          // 110592 B

__global__ __launch_bounds__(256, 2) void gemm_out(float* __restrict__ out) {
    extern __shared__ char smem[];
    const uint32_t sb = smem_u32(smem);
    const int tid = threadIdx.x, wid = tid >> 5, lane = tid & 31;
    const int warp_m = wid & 3, warp_n = wid >> 2;
    const int m_base = blockIdx.x * 128;

    auto load_A = [&](int kc, int st) {
        int rel  = kc >> 1;
        int koff = (kc & 1) * 64;
        const __nv_bfloat16* pah = g_ah + (size_t)rel * NNODES * HF + koff;
        const __nv_bfloat16* pal = g_al + (size_t)rel * NNODES * HF + koff;
        #pragma unroll
        for (int it = 0; it < 4; it++) {
            int id  = it * 256 + tid;
            int row = id >> 3, col = (id & 7) * 8;
            uint32_t doff = (uint32_t)(row * PITCH + col) * 2;
            int gr = m_base + row;
            bool ok = gr < NNODES;
            size_t moff = (size_t)(ok ? gr : 0) * HF + col;
            cp16z(sb + SM_A(st, 0) + doff, pah + moff, ok);
            cp16z(sb + SM_A(st, 1) + doff, pal + moff, ok);
        }
    };
    auto load_B = [&](int kc) {
        int rel  = kc >> 1;
        int koff = (kc & 1) * 64;
        const __nv_bfloat16* pbh = g_bh + rel * HF * HF + koff;
        const __nv_bfloat16* pbl = g_bl + rel * HF * HF + koff;
        #pragma unroll
        for (int it = 0; it < 4; it++) {
            int id  = it * 256 + tid;
            int row = id >> 3, col = (id & 7) * 8;
            uint32_t doff = (uint32_t)(row * PITCH + col) * 2;
            size_t noff = (size_t)row * HF + col;
            cp16(sb + SM_B(0) + doff, pbh + noff);
            cp16(sb + SM_B(1) + doff, pbl + noff);
        }
    };

    float acc[2][8][4];
    #pragma unroll
    for (int mt = 0; mt < 2; mt++)
        #pragma unroll
        for (int ng = 0; ng < 8; ng++)
            #pragma unroll
            for (int q = 0; q < 4; q++) acc[mt][ng][q] = 0.f;

    load_A(0, 0); load_B(0); CP_COMMIT();
    int st = 0;

    const int a_mrow  = warp_m * 32 + ((lane >> 3) & 1) * 8 + (lane & 7);
    const int a_kcol  = ((lane >> 4) & 1) * 8;
    const int b_nrow0 = warp_n * 64 + ((lane >> 4) & 1) * 8 + (lane & 7);
    const int b_kcol  = ((lane >> 3) & 1) * 8;

    for (int kc = 0; kc < 16; kc++) {
        if (kc < 15) { load_A(kc + 1, st ^ 1); CP_COMMIT(); CP_WAIT(1); }
        else         { CP_WAIT(0); }
        __syncthreads();

        #pragma unroll
        for (int ks = 0; ks < 4; ks++) {
            uint32_t ahf[2][4], alf[2][4];
            #pragma unroll
            for (int mt = 0; mt < 2; mt++) {
                uint32_t ao = (uint32_t)((a_mrow + mt * 16) * PITCH + ks * 16 + a_kcol) * 2;
                ldm_x4(ahf[mt][0], ahf[mt][1], ahf[mt][2], ahf[mt][3], sb + SM_A(st, 0) + ao);
                ldm_x4(alf[mt][0], alf[mt][1], alf[mt][2], alf[mt][3], sb + SM_A(st, 1) + ao);
            }
            #pragma unroll
            for (int g = 0; g < 4; g++) {
                uint32_t bh[2][2], bl[2][2];
                uint32_t bo = (uint32_t)((b_nrow0 + g * 16) * PITCH + ks * 16 + b_kcol) * 2;
                ldm_x4(bh[0][0], bh[0][1], bh[1][0], bh[1][1], sb + SM_B(0) + bo);
                ldm_x4(bl[0][0], bl[0][1], bl[1][0], bl[1][1], sb + SM_B(1) + bo);
                #pragma unroll
                for (int h = 0; h < 2; h++) {
                    int ng = g * 2 + h;
                    #pragma unroll
                    for (int mt = 0; mt < 2; mt++) {
                        mma16816(acc[mt][ng], ahf[mt], bh[h]);
                        mma16816(acc[mt][ng], ahf[mt], bl[h]);
                        mma16816(acc[mt][ng], alf[mt], bh[h]);
                    }
                }
            }
        }
        __syncthreads();
        if (kc < 15) { load_B(kc + 1); CP_COMMIT(); }
        st ^= 1;
    }

    // epilogue
    const int er = lane >> 2, ec = (lane & 3) * 2;
    #pragma unroll
    for (int mt = 0; mt < 2; mt++) {
        int r0 = m_base + warp_m * 32 + mt * 16 + er;
        #pragma unroll
        for (int ng = 0; ng < 8; ng++) {
            int c = warp_n * 64 + ng * 8 + ec;
            if (r0 < NNODES)
                *(float2*)(out + (size_t)r0 * HF + c) =
                    make_float2(fmaxf(acc[mt][ng][0], 0.f), fmaxf(acc[mt][ng][1], 0.f));
            if (r0 + 8 < NNODES)
                *(float2*)(out + (size_t)(r0 + 8) * HF + c) =
                    make_float2(fmaxf(acc[mt][ng][2], 0.f), fmaxf(acc[mt][ng][3], 0.f));
        }
    }
}

// ============================================================================
extern "C" void kernel_launch(void* const* d_in, const int* in_sizes, int n_in,
                              void* d_out, int out_size) {
    const float* nodes = (const float*)d_in[0];
    const int*   idx   = (const int*)d_in[1];     // [2, NNZ] int32
    const float* vals  = (const float*)d_in[2];
    const float* W     = (const float*)d_in[3];
    float*       out   = (float*)d_out;

    void* cntp = nullptr;
    cudaGetSymbolAddress(&cntp, g_cnt);
    cudaMemsetAsync(cntp, 0, NNODES * sizeof(int));

    cudaFuncSetAttribute(gemm_out, cudaFuncAttributeMaxDynamicSharedMemorySize, SM_TOTAL);

    build_buckets<<<(NNZ_ + 255) / 256, 256>>>(idx, idx + NNZ_, vals);
    convert_w<<<(RELS * HF * HF + 255) / 256, 256>>>(W);
    aggregate_feats<<<(NNODES * 32 + 255) / 256, 256>>>(nodes);
    gemm_out<<<TILES_M, 256, SM_TOTAL>>>(out);
}

// round 9
// speedup vs baseline: 1.2966x; 1.2966x over previous
#include <cuda_runtime.h>
#include <cuda_bf16.h>
#include <cstdint>

#define NNODES 100000
#define RELS   8
#define HF     128
#define NNZ_   1600000
#define CAP    128
#define TILES_M ((NNODES + 127) / 128)   // 782

// ---- static device scratch ----
__device__ int   g_cnt[NNODES];
__device__ int2  g_bucket[(size_t)NNODES * CAP];                 // {src | rel<<17, bits(val)}
__device__ __nv_bfloat16 g_ah[(size_t)RELS * NNODES * HF];       // agg hi (bf16)
__device__ __nv_bfloat16 g_al[(size_t)RELS * NNODES * HF];       // agg lo (bf16 residual)
__device__ __nv_bfloat16 g_bh[RELS * HF * HF];                   // W hi
__device__ __nv_bfloat16 g_bl[RELS * HF * HF];                   // W lo

// ============================================================================
// helpers (family-portable PTX only: cp.async, ldmatrix, mma.sync)
// ============================================================================
__device__ __forceinline__ uint32_t smem_u32(const void* p) {
    uint32_t a;
    asm("{ .reg .u64 t; cvta.to.shared.u64 t, %1; cvt.u32.u64 %0, t; }" : "=r"(a) : "l"(p));
    return a;
}
__device__ __forceinline__ void cp16(uint32_t dst, const void* src) {
    asm volatile("cp.async.cg.shared.global [%0], [%1], 16;" :: "r"(dst), "l"(src) : "memory");
}
__device__ __forceinline__ void cp16z(uint32_t dst, const void* src, bool ok) {
    int n = ok ? 16 : 0;   // src-size 0 -> zero-fill
    asm volatile("cp.async.cg.shared.global [%0], [%1], 16, %2;" :: "r"(dst), "l"(src), "r"(n) : "memory");
}
#define CP_COMMIT() asm volatile("cp.async.commit_group;" ::: "memory")
#define CP_WAIT(N)  asm volatile("cp.async.wait_group %0;" :: "n"(N) : "memory")

__device__ __forceinline__ void ldm_x4(uint32_t& r0, uint32_t& r1, uint32_t& r2, uint32_t& r3, uint32_t a) {
    asm volatile("ldmatrix.sync.aligned.m8n8.x4.shared.b16 {%0,%1,%2,%3}, [%4];"
                 : "=r"(r0), "=r"(r1), "=r"(r2), "=r"(r3) : "r"(a));
}
__device__ __forceinline__ void mma16816(float* c, const uint32_t* a, const uint32_t* b) {
    asm volatile("mma.sync.aligned.m16n8k16.row.col.f32.bf16.bf16.f32 "
                 "{%0,%1,%2,%3}, {%4,%5,%6,%7}, {%8,%9}, {%0,%1,%2,%3};"
                 : "+f"(c[0]), "+f"(c[1]), "+f"(c[2]), "+f"(c[3])
                 : "r"(a[0]), "r"(a[1]), "r"(a[2]), "r"(a[3]), "r"(b[0]), "r"(b[1]));
}

// ============================================================================
// Phase 1: bucket edges by destination (indices are int32)
// ============================================================================
__global__ void build_buckets(const int* __restrict__ rows,
                              const int* __restrict__ cols,
                              const float* __restrict__ vals) {
    int e = blockIdx.x * blockDim.x + threadIdx.x;
    if (e >= NNZ_) return;
    int row = rows[e];
    int rel = row / NNODES;
    int dst = row - rel * NNODES;
    int src = cols[e];
    if ((unsigned)rel >= RELS || (unsigned)dst >= NNODES || (unsigned)src >= NNODES) return;
    int slot = atomicAdd(&g_cnt[dst], 1);
    if (slot < CAP)
        g_bucket[(size_t)dst * CAP + slot] = make_int2(src | (rel << 17), __float_as_int(vals[e]));
}

// ============================================================================
// Phase 1b: split W (fp32 -> bf16 hi/lo)
// ============================================================================
__global__ void convert_w(const float* __restrict__ W) {
    int i = blockIdx.x * blockDim.x + threadIdx.x;
    if (i >= RELS * HF * HF) return;
    float x = W[i];
    __nv_bfloat16 h = __float2bfloat16_rn(x);
    g_bh[i] = h;
    g_bl[i] = __float2bfloat16_rn(x - __bfloat162float(h));
}

// ============================================================================
// Phase 2: one warp per dst: agg[r][dst][:] = sum val * nodes[src][:]
// (R4 version — simple loop; the MLP unroll regressed due to occupancy loss)
// ============================================================================
__device__ __forceinline__ void split_store(int rel, int dst, int lane, float4 a) {
    size_t base = ((size_t)rel * NNODES + dst) * HF + lane * 4;
    __nv_bfloat16 hx = __float2bfloat16_rn(a.x), hy = __float2bfloat16_rn(a.y);
    __nv_bfloat16 hz = __float2bfloat16_rn(a.z), hw = __float2bfloat16_rn(a.w);
    *(__nv_bfloat162*)(g_ah + base)     = __nv_bfloat162(hx, hy);
    *(__nv_bfloat162*)(g_ah + base + 2) = __nv_bfloat162(hz, hw);
    *(__nv_bfloat162*)(g_al + base) = __nv_bfloat162(
        __float2bfloat16_rn(a.x - __bfloat162float(hx)),
        __float2bfloat16_rn(a.y - __bfloat162float(hy)));
    *(__nv_bfloat162*)(g_al + base + 2) = __nv_bfloat162(
        __float2bfloat16_rn(a.z - __bfloat162float(hz)),
        __float2bfloat16_rn(a.w - __bfloat162float(hw)));
}

__global__ __launch_bounds__(256) void aggregate_feats(const float* __restrict__ nodes) {
    int warp = (blockIdx.x * blockDim.x + threadIdx.x) >> 5;
    int lane = threadIdx.x & 31;
    if (warp >= NNODES) return;
    int cnt = g_cnt[warp];
    if (cnt > CAP) cnt = CAP;

    float4 a0 = {0,0,0,0}, a1 = {0,0,0,0}, a2 = {0,0,0,0}, a3 = {0,0,0,0};
    float4 a4 = {0,0,0,0}, a5 = {0,0,0,0}, a6 = {0,0,0,0}, a7 = {0,0,0,0};

    const int2* bk = g_bucket + (size_t)warp * CAP;
    for (int s = 0; s < cnt; s++) {
        int2 e = bk[s];
        int   src = e.x & 0x1FFFF;
        int   rel = e.x >> 17;
        float v   = __int_as_float(e.y);
        float4 x = *(const float4*)(nodes + (size_t)src * HF + lane * 4);
        #define ACC(A) { A.x += v * x.x; A.y += v * x.y; A.z += v * x.z; A.w += v * x.w; }
        switch (rel) {
            case 0: ACC(a0); break; case 1: ACC(a1); break;
            case 2: ACC(a2); break; case 3: ACC(a3); break;
            case 4: ACC(a4); break; case 5: ACC(a5); break;
            case 6: ACC(a6); break; case 7: ACC(a7); break;
        }
        #undef ACC
    }
    split_store(0, warp, lane, a0); split_store(1, warp, lane, a1);
    split_store(2, warp, lane, a2); split_store(3, warp, lane, a3);
    split_store(4, warp, lane, a4); split_store(5, warp, lane, a5);
    split_store(6, warp, lane, a6); split_store(7, warp, lane, a7);
}

// ============================================================================
// Phase 3: out = relu( agg_flat[100k,1024] @ Wcat[128,1024]^T )
// R4 structure (A+B double-buffered, 147KB smem, 1 CTA/SM) with ONE change:
// pass-major MMA ordering — each acc reused every 32 independent MMAs
// instead of 3 back-to-back dependent MMAs (kills the HMMA latency stall).
// ============================================================================
#define PITCH   72                        // bf16 per smem row (64 + 8 pad)
#define AT_SZ   (128 * PITCH * 2)         // 18432 B per 128x64 tile
#define SM_A(st, h)  ((uint32_t)((st) * 2 * AT_SZ + (h) * AT_SZ))
#define SM_B(st, h)  ((uint32_t)(4 * AT_SZ + (st) * 2 * AT_SZ + (h) * AT_SZ))
#define SM_TOTAL     (8 * AT_SZ)          // 147456 B

__global__ __launch_bounds__(256, 1) void gemm_out(float* __restrict__ out) {
    extern __shared__ char smem[];
    const uint32_t sb = smem_u32(smem);
    const int tid = threadIdx.x, wid = tid >> 5, lane = tid & 31;
    const int warp_m = wid & 3, warp_n = wid >> 2;
    const int m_base = blockIdx.x * 128;

    auto load_chunk = [&](int kc, int st) {
        int rel  = kc >> 1;
        int koff = (kc & 1) * 64;
        const __nv_bfloat16* pah = g_ah + (size_t)rel * NNODES * HF + koff;
        const __nv_bfloat16* pal = g_al + (size_t)rel * NNODES * HF + koff;
        const __nv_bfloat16* pbh = g_bh + rel * HF * HF + koff;
        const __nv_bfloat16* pbl = g_bl + rel * HF * HF + koff;
        #pragma unroll
        for (int it = 0; it < 4; it++) {
            int id  = it * 256 + tid;         // 0..1023
            int row = id >> 3;                // 0..127
            int col = (id & 7) * 8;           // 0..56
            uint32_t doff = (uint32_t)(row * PITCH + col) * 2;
            int gr = m_base + row;
            bool ok = gr < NNODES;
            size_t moff = (size_t)(ok ? gr : 0) * HF + col;
            cp16z(sb + SM_A(st, 0) + doff, pah + moff, ok);
            cp16z(sb + SM_A(st, 1) + doff, pal + moff, ok);
            size_t noff = (size_t)row * HF + col;
            cp16(sb + SM_B(st, 0) + doff, pbh + noff);
            cp16(sb + SM_B(st, 1) + doff, pbl + noff);
        }
    };

    float acc[2][8][4];
    #pragma unroll
    for (int mt = 0; mt < 2; mt++)
        #pragma unroll
        for (int ng = 0; ng < 8; ng++)
            #pragma unroll
            for (int q = 0; q < 4; q++) acc[mt][ng][q] = 0.f;

    load_chunk(0, 0); CP_COMMIT();
    int st = 0;

    const int a_mrow  = warp_m * 32 + ((lane >> 3) & 1) * 8 + (lane & 7);
    const int a_kcol  = ((lane >> 4) & 1) * 8;
    const int b_nrow0 = warp_n * 64 + ((lane >> 4) & 1) * 8 + (lane & 7);
    const int b_kcol  = ((lane >> 3) & 1) * 8;

    for (int kc = 0; kc < 16; kc++) {
        if (kc < 15) { load_chunk(kc + 1, st ^ 1); CP_COMMIT(); CP_WAIT(1); }
        else         { CP_WAIT(0); }
        __syncthreads();

        #pragma unroll
        for (int ks = 0; ks < 4; ks++) {
            uint32_t ahf[2][4], alf[2][4], bhf[8][2], blf[8][2];
            #pragma unroll
            for (int mt = 0; mt < 2; mt++) {
                uint32_t ao = (uint32_t)((a_mrow + mt * 16) * PITCH + ks * 16 + a_kcol) * 2;
                ldm_x4(ahf[mt][0], ahf[mt][1], ahf[mt][2], ahf[mt][3], sb + SM_A(st, 0) + ao);
                ldm_x4(alf[mt][0], alf[mt][1], alf[mt][2], alf[mt][3], sb + SM_A(st, 1) + ao);
            }
            #pragma unroll
            for (int g = 0; g < 4; g++) {
                uint32_t bo = (uint32_t)((b_nrow0 + g * 16) * PITCH + ks * 16 + b_kcol) * 2;
                ldm_x4(bhf[g*2][0], bhf[g*2][1], bhf[g*2+1][0], bhf[g*2+1][1], sb + SM_B(st, 0) + bo);
                ldm_x4(blf[g*2][0], blf[g*2][1], blf[g*2+1][0], blf[g*2+1][1], sb + SM_B(st, 1) + bo);
            }
            // pass-major: 32 independent MMAs between reuses of any acc tile
            #pragma unroll
            for (int p = 0; p < 3; p++) {
                #pragma unroll
                for (int mt = 0; mt < 2; mt++)
                    #pragma unroll
                    for (int ng = 0; ng < 8; ng++) {
                        const uint32_t* af = (p == 2) ? alf[mt] : ahf[mt];
                        const uint32_t* bf = (p == 1) ? blf[ng] : bhf[ng];
                        mma16816(acc[mt][ng], af, bf);
                    }
            }
        }
        __syncthreads();
        st ^= 1;
    }

    // epilogue: c-frag thread t -> rows (t/4, t/4+8), cols (t%4)*2..+1
    const int er = lane >> 2, ec = (lane & 3) * 2;
    #pragma unroll
    for (int mt = 0; mt < 2; mt++) {
        int r0 = m_base + warp_m * 32 + mt * 16 + er;
        #pragma unroll
        for (int ng = 0; ng < 8; ng++) {
            int c = warp_n * 64 + ng * 8 + ec;
            if (r0 < NNODES)
                *(float2*)(out + (size_t)r0 * HF + c) =
                    make_float2(fmaxf(acc[mt][ng][0], 0.f), fmaxf(acc[mt][ng][1], 0.f));
            if (r0 + 8 < NNODES)
                *(float2*)(out + (size_t)(r0 + 8) * HF + c) =
                    make_float2(fmaxf(acc[mt][ng][2], 0.f), fmaxf(acc[mt][ng][3], 0.f));
        }
    }
}

// ============================================================================
extern "C" void kernel_launch(void* const* d_in, const int* in_sizes, int n_in,
                              void* d_out, int out_size) {
    const float* nodes = (const float*)d_in[0];
    const int*   idx   = (const int*)d_in[1];     // [2, NNZ] int32
    const float* vals  = (const float*)d_in[2];
    const float* W     = (const float*)d_in[3];
    float*       out   = (float*)d_out;

    void* cntp = nullptr;
    cudaGetSymbolAddress(&cntp, g_cnt);
    cudaMemsetAsync(cntp, 0, NNODES * sizeof(int));

    cudaFuncSetAttribute(gemm_out, cudaFuncAttributeMaxDynamicSharedMemorySize, SM_TOTAL);

    build_buckets<<<(NNZ_ + 255) / 256, 256>>>(idx, idx + NNZ_, vals);
    convert_w<<<(RELS * HF * HF + 255) / 256, 256>>>(W);
    aggregate_feats<<<(NNODES * 32 + 255) / 256, 256>>>(nodes);
    gemm_out<<<TILES_M, 256, SM_TOTAL>>>(out);
}

// round 13
// speedup vs baseline: 1.3817x; 1.0656x over previous
#include <cuda_runtime.h>
#include <cuda_bf16.h>
#include <cstdint>

#define NNODES 100000
#define RELS   8
#define HF     128
#define NNZ_   1600000
#define CAP    128
#define TILES_M ((NNODES + 127) / 128)   // 782

// ---- static device scratch ----
__device__ int   g_cnt[NNODES];
__device__ int2  g_bucket[(size_t)NNODES * CAP];                 // {src | rel<<17, bits(val)}
__device__ __nv_bfloat16 g_ah[(size_t)RELS * NNODES * HF];       // agg hi (bf16)
__device__ __nv_bfloat16 g_al[(size_t)RELS * NNODES * HF];       // agg lo (bf16 residual)
__device__ __nv_bfloat16 g_bh[RELS * HF * HF];                   // W hi
__device__ __nv_bfloat16 g_bl[RELS * HF * HF];                   // W lo

// ============================================================================
// helpers (family-portable PTX only: cp.async, ldmatrix, mma.sync)
// ============================================================================
__device__ __forceinline__ uint32_t smem_u32(const void* p) {
    uint32_t a;
    asm("{ .reg .u64 t; cvta.to.shared.u64 t, %1; cvt.u32.u64 %0, t; }" : "=r"(a) : "l"(p));
    return a;
}
__device__ __forceinline__ void cp16(uint32_t dst, const void* src) {
    asm volatile("cp.async.cg.shared.global [%0], [%1], 16;" :: "r"(dst), "l"(src) : "memory");
}
__device__ __forceinline__ void cp16z(uint32_t dst, const void* src, bool ok) {
    int n = ok ? 16 : 0;   // src-size 0 -> zero-fill
    asm volatile("cp.async.cg.shared.global [%0], [%1], 16, %2;" :: "r"(dst), "l"(src), "r"(n) : "memory");
}
#define CP_COMMIT() asm volatile("cp.async.commit_group;" ::: "memory")
#define CP_WAIT(N)  asm volatile("cp.async.wait_group %0;" :: "n"(N) : "memory")

__device__ __forceinline__ void ldm_x4(uint32_t& r0, uint32_t& r1, uint32_t& r2, uint32_t& r3, uint32_t a) {
    asm volatile("ldmatrix.sync.aligned.m8n8.x4.shared.b16 {%0,%1,%2,%3}, [%4];"
                 : "=r"(r0), "=r"(r1), "=r"(r2), "=r"(r3) : "r"(a));
}
__device__ __forceinline__ void mma16816(float* c, const uint32_t* a, const uint32_t* b) {
    asm volatile("mma.sync.aligned.m16n8k16.row.col.f32.bf16.bf16.f32 "
                 "{%0,%1,%2,%3}, {%4,%5,%6,%7}, {%8,%9}, {%0,%1,%2,%3};"
                 : "+f"(c[0]), "+f"(c[1]), "+f"(c[2]), "+f"(c[3])
                 : "r"(a[0]), "r"(a[1]), "r"(a[2]), "r"(a[3]), "r"(b[0]), "r"(b[1]));
}

// ============================================================================
// Phase 1: bucket edges by destination (indices are int32)
// ============================================================================
__global__ void build_buckets(const int* __restrict__ rows,
                              const int* __restrict__ cols,
                              const float* __restrict__ vals) {
    int e = blockIdx.x * blockDim.x + threadIdx.x;
    if (e >= NNZ_) return;
    int row = rows[e];
    int rel = row / NNODES;
    int dst = row - rel * NNODES;
    int src = cols[e];
    if ((unsigned)rel >= RELS || (unsigned)dst >= NNODES || (unsigned)src >= NNODES) return;
    int slot = atomicAdd(&g_cnt[dst], 1);
    if (slot < CAP)
        g_bucket[(size_t)dst * CAP + slot] = make_int2(src | (rel << 17), __float_as_int(vals[e]));
}

// ============================================================================
// Phase 1b: split W (fp32 -> bf16 hi/lo)
// ============================================================================
__global__ void convert_w(const float* __restrict__ W) {
    int i = blockIdx.x * blockDim.x + threadIdx.x;
    if (i >= RELS * HF * HF) return;
    float x = W[i];
    __nv_bfloat16 h = __float2bfloat16_rn(x);
    g_bh[i] = h;
    g_bl[i] = __float2bfloat16_rn(x - __bfloat162float(h));
}

// ============================================================================
// Phase 2: one warp per dst: agg[r][dst][:] = sum val * nodes[src][:]
// Depth-2 software pipeline: next edge's gather issued before current FMAs.
// ============================================================================
__device__ __forceinline__ void split_store(int rel, int dst, int lane, float4 a) {
    size_t base = ((size_t)rel * NNODES + dst) * HF + lane * 4;
    __nv_bfloat16 hx = __float2bfloat16_rn(a.x), hy = __float2bfloat16_rn(a.y);
    __nv_bfloat16 hz = __float2bfloat16_rn(a.z), hw = __float2bfloat16_rn(a.w);
    *(__nv_bfloat162*)(g_ah + base)     = __nv_bfloat162(hx, hy);
    *(__nv_bfloat162*)(g_ah + base + 2) = __nv_bfloat162(hz, hw);
    *(__nv_bfloat162*)(g_al + base) = __nv_bfloat162(
        __float2bfloat16_rn(a.x - __bfloat162float(hx)),
        __float2bfloat16_rn(a.y - __bfloat162float(hy)));
    *(__nv_bfloat162*)(g_al + base + 2) = __nv_bfloat162(
        __float2bfloat16_rn(a.z - __bfloat162float(hz)),
        __float2bfloat16_rn(a.w - __bfloat162float(hw)));
}

__global__ __launch_bounds__(256) void aggregate_feats(const float* __restrict__ nodes) {
    int warp = (blockIdx.x * blockDim.x + threadIdx.x) >> 5;
    int lane = threadIdx.x & 31;
    if (warp >= NNODES) return;
    int cnt = g_cnt[warp];
    if (cnt > CAP) cnt = CAP;

    float4 a0 = {0,0,0,0}, a1 = {0,0,0,0}, a2 = {0,0,0,0}, a3 = {0,0,0,0};
    float4 a4 = {0,0,0,0}, a5 = {0,0,0,0}, a6 = {0,0,0,0}, a7 = {0,0,0,0};

    const int2* bk = g_bucket + (size_t)warp * CAP;

    #define ACC(E, X) {                                                        \
        float v = __int_as_float((E).y);                                       \
        switch ((E).x >> 17) {                                                 \
            case 0: a0.x+=v*(X).x; a0.y+=v*(X).y; a0.z+=v*(X).z; a0.w+=v*(X).w; break; \
            case 1: a1.x+=v*(X).x; a1.y+=v*(X).y; a1.z+=v*(X).z; a1.w+=v*(X).w; break; \
            case 2: a2.x+=v*(X).x; a2.y+=v*(X).y; a2.z+=v*(X).z; a2.w+=v*(X).w; break; \
            case 3: a3.x+=v*(X).x; a3.y+=v*(X).y; a3.z+=v*(X).z; a3.w+=v*(X).w; break; \
            case 4: a4.x+=v*(X).x; a4.y+=v*(X).y; a4.z+=v*(X).z; a4.w+=v*(X).w; break; \
            case 5: a5.x+=v*(X).x; a5.y+=v*(X).y; a5.z+=v*(X).z; a5.w+=v*(X).w; break; \
            case 6: a6.x+=v*(X).x; a6.y+=v*(X).y; a6.z+=v*(X).z; a6.w+=v*(X).w; break; \
            case 7: a7.x+=v*(X).x; a7.y+=v*(X).y; a7.z+=v*(X).z; a7.w+=v*(X).w; break; \
        }                                                                      \
    }

    if (cnt > 0) {
        int2   e = bk[0];
        float4 x = *(const float4*)(nodes + (size_t)(e.x & 0x1FFFF) * HF + lane * 4);
        for (int s = 1; s < cnt; s++) {
            int2   en = bk[s];
            float4 xn = *(const float4*)(nodes + (size_t)(en.x & 0x1FFFF) * HF + lane * 4);
            ACC(e, x);
            e = en; x = xn;
        }
        ACC(e, x);
    }
    #undef ACC

    split_store(0, warp, lane, a0); split_store(1, warp, lane, a1);
    split_store(2, warp, lane, a2); split_store(3, warp, lane, a3);
    split_store(4, warp, lane, a4); split_store(5, warp, lane, a5);
    split_store(6, warp, lane, a6); split_store(7, warp, lane, a7);
}

// ============================================================================
// Phase 3: out = relu( agg_flat[100k,1024] @ Wcat[128,1024]^T )
// mma.sync bf16 3-pass split. Block 128x128, 8 warps 4x2.
// 3-STAGE cp.async pipeline (loads issued 2 chunks ahead, wait_group 2)
// to hide per-chunk DRAM landing time. 221KB smem, 1 CTA/SM.
// ============================================================================
#define PITCH   72                        // bf16 per smem row (64 + 8 pad)
#define AT_SZ   (128 * PITCH * 2)         // 18432 B per 128x64 tile
#define NSTAGE  3
#define ST_SZ   (4 * AT_SZ)               // A-hi, A-lo, B-hi, B-lo per stage
#define SM_A(st, h)  ((uint32_t)((st) * ST_SZ + (h) * AT_SZ))
#define SM_B(st, h)  ((uint32_t)((st) * ST_SZ + 2 * AT_SZ + (h) * AT_SZ))
#define SM_TOTAL     (NSTAGE * ST_SZ)     // 221184 B

__global__ __launch_bounds__(256, 1) void gemm_out(float* __restrict__ out) {
    extern __shared__ char smem[];
    const uint32_t sb = smem_u32(smem);
    const int tid = threadIdx.x, wid = tid >> 5, lane = tid & 31;
    const int warp_m = wid & 3, warp_n = wid >> 2;
    const int m_base = blockIdx.x * 128;

    auto load_chunk = [&](int kc, int st) {
        int rel  = kc >> 1;
        int koff = (kc & 1) * 64;
        const __nv_bfloat16* pah = g_ah + (size_t)rel * NNODES * HF + koff;
        const __nv_bfloat16* pal = g_al + (size_t)rel * NNODES * HF + koff;
        const __nv_bfloat16* pbh = g_bh + rel * HF * HF + koff;
        const __nv_bfloat16* pbl = g_bl + rel * HF * HF + koff;
        #pragma unroll
        for (int it = 0; it < 4; it++) {
            int id  = it * 256 + tid;         // 0..1023
            int row = id >> 3;                // 0..127
            int col = (id & 7) * 8;           // 0..56
            uint32_t doff = (uint32_t)(row * PITCH + col) * 2;
            int gr = m_base + row;
            bool ok = gr < NNODES;
            size_t moff = (size_t)(ok ? gr : 0) * HF + col;
            cp16z(sb + SM_A(st, 0) + doff, pah + moff, ok);
            cp16z(sb + SM_A(st, 1) + doff, pal + moff, ok);
            size_t noff = (size_t)row * HF + col;
            cp16(sb + SM_B(st, 0) + doff, pbh + noff);
            cp16(sb + SM_B(st, 1) + doff, pbl + noff);
        }
    };

    float acc[2][8][4];
    #pragma unroll
    for (int mt = 0; mt < 2; mt++)
        #pragma unroll
        for (int ng = 0; ng < 8; ng++)
            #pragma unroll
            for (int q = 0; q < 4; q++) acc[mt][ng][q] = 0.f;

    // prologue: 2 chunks in flight
    load_chunk(0, 0); CP_COMMIT();
    load_chunk(1, 1); CP_COMMIT();

    const int a_mrow  = warp_m * 32 + ((lane >> 3) & 1) * 8 + (lane & 7);
    const int a_kcol  = ((lane >> 4) & 1) * 8;
    const int b_nrow0 = warp_n * 64 + ((lane >> 4) & 1) * 8 + (lane & 7);
    const int b_kcol  = ((lane >> 3) & 1) * 8;

    for (int kc = 0; kc < 16; kc++) {
        const int st = kc % NSTAGE;
        if (kc + 2 < 16) { load_chunk(kc + 2, (kc + 2) % NSTAGE); CP_COMMIT(); CP_WAIT(2); }
        else if (kc == 14) { CP_WAIT(1); }
        else               { CP_WAIT(0); }
        __syncthreads();

        #pragma unroll
        for (int ks = 0; ks < 4; ks++) {
            uint32_t ahf[2][4], alf[2][4], bhf[8][2], blf[8][2];
            #pragma unroll
            for (int mt = 0; mt < 2; mt++) {
                uint32_t ao = (uint32_t)((a_mrow + mt * 16) * PITCH + ks * 16 + a_kcol) * 2;
                ldm_x4(ahf[mt][0], ahf[mt][1], ahf[mt][2], ahf[mt][3], sb + SM_A(st, 0) + ao);
                ldm_x4(alf[mt][0], alf[mt][1], alf[mt][2], alf[mt][3], sb + SM_A(st, 1) + ao);
            }
            #pragma unroll
            for (int g = 0; g < 4; g++) {
                uint32_t bo = (uint32_t)((b_nrow0 + g * 16) * PITCH + ks * 16 + b_kcol) * 2;
                ldm_x4(bhf[g*2][0], bhf[g*2][1], bhf[g*2+1][0], bhf[g*2+1][1], sb + SM_B(st, 0) + bo);
                ldm_x4(blf[g*2][0], blf[g*2][1], blf[g*2+1][0], blf[g*2+1][1], sb + SM_B(st, 1) + bo);
            }
            #pragma unroll
            for (int p = 0; p < 3; p++) {
                #pragma unroll
                for (int mt = 0; mt < 2; mt++)
                    #pragma unroll
                    for (int ng = 0; ng < 8; ng++) {
                        const uint32_t* af = (p == 2) ? alf[mt] : ahf[mt];
                        const uint32_t* bf = (p == 1) ? blf[ng] : bhf[ng];
                        mma16816(acc[mt][ng], af, bf);
                    }
            }
        }
        __syncthreads();
    }

    // epilogue: c-frag thread t -> rows (t/4, t/4+8), cols (t%4)*2..+1
    const int er = lane >> 2, ec = (lane & 3) * 2;
    #pragma unroll
    for (int mt = 0; mt < 2; mt++) {
        int r0 = m_base + warp_m * 32 + mt * 16 + er;
        #pragma unroll
        for (int ng = 0; ng < 8; ng++) {
            int c = warp_n * 64 + ng * 8 + ec;
            if (r0 < NNODES)
                *(float2*)(out + (size_t)r0 * HF + c) =
                    make_float2(fmaxf(acc[mt][ng][0], 0.f), fmaxf(acc[mt][ng][1], 0.f));
            if (r0 + 8 < NNODES)
                *(float2*)(out + (size_t)(r0 + 8) * HF + c) =
                    make_float2(fmaxf(acc[mt][ng][2], 0.f), fmaxf(acc[mt][ng][3], 0.f));
        }
    }
}

// ============================================================================
extern "C" void kernel_launch(void* const* d_in, const int* in_sizes, int n_in,
                              void* d_out, int out_size) {
    const float* nodes = (const float*)d_in[0];
    const int*   idx   = (const int*)d_in[1];     // [2, NNZ] int32
    const float* vals  = (const float*)d_in[2];
    const float* W     = (const float*)d_in[3];
    float*       out   = (float*)d_out;

    void* cntp = nullptr;
    cudaGetSymbolAddress(&cntp, g_cnt);
    cudaMemsetAsync(cntp, 0, NNODES * sizeof(int));

    cudaFuncSetAttribute(gemm_out, cudaFuncAttributeMaxDynamicSharedMemorySize, SM_TOTAL);

    build_buckets<<<(NNZ_ + 255) / 256, 256>>>(idx, idx + NNZ_, vals);
    convert_w<<<(RELS * HF * HF + 255) / 256, 256>>>(W);
    aggregate_feats<<<(NNODES * 32 + 255) / 256, 256>>>(nodes);
    gemm_out<<<TILES_M, 256, SM_TOTAL>>>(out);
}